// round 15
// baseline (speedup 1.0000x reference)
#include <cuda_runtime.h>
#include <stdint.h>

// ---------------------------------------------------------------------------
// BlurModel: 9x9 box blur -> per-patch sequential threshold search ->
// binarize -> morphological close, 2048x2048 f32.
// R15: select reverted to monolithic smem-hist (R10 split proven neutral,
//      its merge overhead removed); blur loses hist zeroing; close as R14.
// 3 launches.
// ---------------------------------------------------------------------------

#define W      2048
#define NPX    (W * W)
#define WORDS  64
#define NPAT   64
#define NB     8192
#define VLO    0.40f
#define VSC    40960.0f      // NB / 0.2
#define CAP    512

__device__ float g_B[NPX];
__device__ float g_vd[NPAT];
__device__ float g_vu[NPAT];

// ---------------------------------------------------------------------------
__device__ __forceinline__ int bin_of(float v) {
    float f = (v - VLO) * VSC;
    int b = (int)floorf(f);
    return b < 0 ? 0 : (b > NB - 1 ? NB - 1 : b);
}

// ---------------------------------------------------------------------------
// K1: fused 9x9 separable box blur. Horizontal pass reads global float4
// directly; only hsum tile lives in smem. Tile 64x32 out, halo 4.
// 256 threads, 2048 blocks.
__global__ void k_blur(const float* __restrict__ x,
                       const float* __restrict__ kptr) {
    __shared__ __align__(16) float hs[40][64];
    int c0 = blockIdx.x << 6;
    int r0 = blockIdx.y << 5;
    int tid = threadIdx.x;
    float kf = __ldg(kptr);

    // horizontal 9-sum: task = 4 adjacent outputs of one row, reading
    // global cols (c0+c-4 .. c0+c+7) as 3 aligned float4 (zero padded).
    {
        const float4* x4 = (const float4*)x;
        for (int i = tid; i < 40 * 16; i += 256) {
            int row = i >> 4, g = i & 15;
            int c = g << 2;
            int gr = r0 - 4 + row;
            int gbase = c0 + c - 4;
            float4 a = make_float4(0.f, 0.f, 0.f, 0.f);
            float4 b = a, d = a;
            if (gr >= 0 && gr < W) {
                const float4* rp = x4 + ((gr << 11) >> 2);
                if (gbase >= 0)          a = rp[(gbase     ) >> 2];
                                         b = rp[(gbase + 4 ) >> 2];
                if (gbase + 8 < W)       d = rp[(gbase + 8 ) >> 2];
            }
            float f0 = a.x, f1 = a.y, f2 = a.z, f3 = a.w;
            float f4 = b.x, f5 = b.y, f6 = b.z, f7 = b.w;
            float f8 = d.x, f9 = d.y, f10 = d.z, f11 = d.w;
            float4 o;
            o.x = ((((((((f0 + f1) + f2) + f3) + f4) + f5) + f6) + f7) + f8);
            o.y = ((((((((f1 + f2) + f3) + f4) + f5) + f6) + f7) + f8) + f9);
            o.z = ((((((((f2 + f3) + f4) + f5) + f6) + f7) + f8) + f9) + f10);
            o.w = ((((((((f3 + f4) + f5) + f6) + f7) + f8) + f9) + f10) + f11);
            *(float4*)&hs[row][c] = o;
        }
    }
    __syncthreads();

    // vertical 9-sum: thread = 8 consecutive output rows of one column.
    {
        int oc = tid & 63;
        int rg = tid >> 6;
        int base = rg << 3;
        float h[16];
#pragma unroll
        for (int k = 0; k < 16; ++k) h[k] = hs[base + k][oc];
        int gc = c0 + oc;
#pragma unroll
        for (int j = 0; j < 8; ++j) {
            float s = h[j];
#pragma unroll
            for (int k = 1; k < 9; ++k) s += h[j + k];
            int gr = r0 + base + j;
            g_B[(gr << 11) + gc] = s * kf;
        }
    }
}

// ---------------------------------------------------------------------------
__device__ float kth_largest(const float* a, int n, int k) {
    if (n <= 0) return 0.5f;
    if (k >= n) k = n - 1;
    for (int i = 0; i < n; ++i) {
        float v = a[i];
        int g = 0, e = 0;
        for (int j = 0; j < n; ++j) {
            if (a[j] > v) g++;
            else if (a[j] == v) e++;
        }
        if (g <= k && k < g + e) return v;
    }
    return a[0];
}

// K2: per-patch order statistics via SHARED histogram. 64 blocks x 1024 thr.
__global__ void k_select() {
    int p = blockIdx.x;
    int t = threadIdx.x;
    int lane = t & 31, wid = t >> 5;

    __shared__ unsigned hist[NB];          // 32 KB
    __shared__ unsigned warpSuf[32];
    __shared__ int s_binD, s_rD, s_binU, s_rU;
    __shared__ float listD[CAP];
    __shared__ float listU[CAP];
    __shared__ int cntD, cntU;

#pragma unroll
    for (int i = 0; i < NB / 1024; ++i) hist[t + i * 1024] = 0u;
    if (t == 0) { cntD = 0; cntU = 0; }
    __syncthreads();

    int pr = (p >> 3) << 8, pc = (p & 7) << 8;
    const float4* B4 = (const float4*)g_B;

    // pass 1: build histogram (shared atomics, low conflict degree)
    for (int i = t; i < 16384; i += 1024) {
        int rr = pr + (i >> 6);
        int cc = pc + ((i & 63) << 2);
        float4 v = B4[((rr << 11) + cc) >> 2];
        atomicAdd(&hist[bin_of(v.x)], 1u);
        atomicAdd(&hist[bin_of(v.y)], 1u);
        atomicAdd(&hist[bin_of(v.z)], 1u);
        atomicAdd(&hist[bin_of(v.w)], 1u);
    }
    __syncthreads();

    // segment sums: 8 bins per thread
    unsigned segv = 0;
#pragma unroll
    for (int b = 0; b < 8; ++b) segv += hist[t * 8 + b];

    // warp-level inclusive suffix sum
    unsigned suf = segv;
#pragma unroll
    for (int off = 1; off < 32; off <<= 1) {
        unsigned v = __shfl_down_sync(0xFFFFFFFFu, suf, off);
        if (lane + off < 32) suf += v;
    }
    unsigned wtot = __shfl_sync(0xFFFFFFFFu, suf, 0);
    if (lane == 0) warpSuf[wid] = wtot;
    __syncthreads();
    if (wid == 0) {
        unsigned tot = warpSuf[lane];
        unsigned ss = tot;
#pragma unroll
        for (int off = 1; off < 32; off <<= 1) {
            unsigned v = __shfl_down_sync(0xFFFFFFFFu, ss, off);
            if (lane + off < 32) ss += v;
        }
        warpSuf[lane] = ss - tot;          // exclusive suffix of warp totals
    }
    __syncthreads();

    unsigned incl = suf + warpSuf[wid];
    unsigned above = incl - segv;

    bool frame = (p < 8) || (p >= 56) || ((p & 7) == 0) || ((p & 7) == 7);
    float lo = frame ? (0.47f - 0.05f) : 0.47f;
    float hiT = 0.43f;
    const float inv = 1.0f / 65536.0f;
    int Clo = (int)ceilf(lo * 65536.0f);
    while ((float)Clo * inv < lo) Clo++;
    while (Clo > 0 && (float)(Clo - 1) * inv >= lo) Clo--;
    int Chi = (int)floorf(hiT * 65536.0f);
    while ((float)(Chi + 1) * inv <= hiT) Chi++;
    while (Chi > 0 && (float)Chi * inv > hiT) Chi--;
    int kd = Clo - 1;
    int ku = Chi;

    if ((unsigned)kd >= above && (unsigned)kd < incl) {
        unsigned S = above;
        for (int b = 7; b >= 0; --b) {
            unsigned hb = hist[t * 8 + b];
            if ((unsigned)kd < S + hb) { s_binD = t * 8 + b; s_rD = (int)((unsigned)kd - S); break; }
            S += hb;
        }
    }
    if ((unsigned)ku >= above && (unsigned)ku < incl) {
        unsigned S = above;
        for (int b = 7; b >= 0; --b) {
            unsigned hb = hist[t * 8 + b];
            if ((unsigned)ku < S + hb) { s_binU = t * 8 + b; s_rU = (int)((unsigned)ku - S); break; }
            S += hb;
        }
    }
    __syncthreads();

    // pass 2: collect candidate values of the two bins (L2-resident reads)
    int binD = s_binD, binU = s_binU;
    for (int i = t; i < 16384; i += 1024) {
        int rr = pr + (i >> 6);
        int cc = pc + ((i & 63) << 2);
        float4 v = B4[((rr << 11) + cc) >> 2];
        float vv[4] = {v.x, v.y, v.z, v.w};
#pragma unroll
        for (int q = 0; q < 4; ++q) {
            int b = bin_of(vv[q]);
            if (b == binD) {
                int pos = atomicAdd(&cntD, 1);
                if (pos < CAP) listD[pos] = vv[q];
            }
            if (binU != binD && b == binU) {
                int pos = atomicAdd(&cntU, 1);
                if (pos < CAP) listU[pos] = vv[q];
            }
        }
    }
    __syncthreads();

    if (t == 0) {
        int nD = cntD < CAP ? cntD : CAP;
        g_vd[p] = kth_largest(listD, nD, s_rD);
        if (binU == binD) {
            g_vu[p] = kth_largest(listD, nD, s_rU);
        } else {
            int nU = cntU < CAP ? cntU : CAP;
            g_vu[p] = kth_largest(listU, nU, s_rU);
        }
    }
}

// ---------------------------------------------------------------------------
// K3: fused close. Grid (8, 32) = 256 blocks: tile 256 cols x 64 rows.
// 512 threads. bin rows r0-8..r0+71 (80), words wbase-2..wbase+9 (12).
__global__ void k_close(float* __restrict__ out) {
    __shared__ unsigned sbin[80][12];
    __shared__ unsigned sdh[80][12];   // dilH: word j = global wbase-1+j, j=0..9
    __shared__ unsigned sdv[72][12];   // dilV: row dr = global r0-4+dr
    __shared__ unsigned seh[72][8];    // eroH
    __shared__ unsigned sfw[64][8];    // final words
    __shared__ float svd[NPAT], svu[NPAT];
    __shared__ float sth[NPAT];
    int wbase = blockIdx.x << 3;
    int r0 = blockIdx.y << 6;
    int tid = threadIdx.x;
    int warpId = tid >> 5, lane = tid & 31;

    if (tid < NPAT) { svd[tid] = g_vd[tid]; svu[tid] = g_vu[tid]; }
    __syncthreads();
    if (tid == 0) {
        float t = 0.5f;
        for (int p = 0; p < NPAT; ++p) {
            float vd = svd[p], vu = svu[p];
            int guard = 0;
            while (t >= vd && guard < 1000000) {
                guard++;
                bool jumped = false;
                if (t >= 0.25f && t < 1.0f) {
                    float bandlo = (t >= 0.5f) ? 0.5f : 0.25f;
                    int ulps     = (t >= 0.5f) ? 839 : 1678;
                    float tgt = fmaxf(vd, bandlo);
                    int mt = __float_as_int(t), mv = __float_as_int(tgt);
                    int kj = (mt - mv) / ulps - 1;
                    if (kj > 0) { t = __int_as_float(mt - kj * ulps); jumped = true; }
                }
                if (!jumped) t = t - 5e-5f;
            }
            guard = 0;
            while (t < vu && guard < 2000000) {
                guard++;
                bool jumped = false;
                if (t >= 0.25f && t < 1.0f) {
                    float bandhi = (t >= 0.5f) ? 1.0f : 0.5f;
                    int ulps     = (t >= 0.5f) ? 84 : 168;
                    float tgt = fminf(vu, bandhi);
                    int mt = __float_as_int(t), mv = __float_as_int(tgt);
                    int kj = (mv - mt) / ulps - 1;
                    if (kj > 0) { t = __int_as_float(mt + kj * ulps); jumped = true; }
                }
                if (!jumped) t = t + 5e-6f;
            }
            sth[p] = t;
        }
    }
    __syncthreads();

    // binarize 80 rows x 12 words: warp task = 4 words of one row
#pragma unroll 2
    for (int tsk = warpId; tsk < 80 * 3; tsk += 16) {
        int row = tsk / 3, qw = tsk - row * 3;
        int tw = (qw << 2) + (lane >> 3);
        int gw = wbase - 2 + tw;
        int gr = r0 - 8 + row;
        unsigned nib = 0;
        if (gr >= 0 && gr < W && gw >= 0 && gw < WORDS) {
            float th = sth[((gr >> 8) << 3) | (gw >> 3)];
            const float4* rp = (const float4*)(g_B + (gr << 11));
            float4 v = rp[(gw << 3) + (lane & 7)];
            nib = (unsigned)(v.x > th) | ((unsigned)(v.y > th) << 1)
                | ((unsigned)(v.z > th) << 2) | ((unsigned)(v.w > th) << 3);
        }
        unsigned x = nib | (__shfl_xor_sync(0xFFFFFFFFu, nib, 1) << 4);
        x = x | (__shfl_xor_sync(0xFFFFFFFFu, x, 2) << 8);
        x = x | (__shfl_xor_sync(0xFFFFFFFFu, x, 4) << 16);
        if ((lane & 7) == 0) sbin[row][tw] = x;
    }
    __syncthreads();

    // horizontal dilate (pad 0): j = 0..9
    for (int i = tid; i < 80 * 10; i += 512) {
        int row = i / 10, j = i - row * 10;
        unsigned curw = sbin[row][j + 1];
        unsigned left = sbin[row][j];
        unsigned right = sbin[row][j + 2];
        unsigned long long a = ((unsigned long long)curw << 32) | left;
        unsigned long long b = ((unsigned long long)right << 32) | curw;
        unsigned o = curw;
#pragma unroll
        for (int k = 1; k <= 4; ++k) {
            o |= (unsigned)(a >> (32 - k));
            o |= (unsigned)(b >> k);
        }
        sdh[row][j] = o;
    }
    __syncthreads();

    // vertical dilate (pad 0): dr = 0..71
    for (int i = tid; i < 72 * 10; i += 512) {
        int dr = i / 10, j = i - dr * 10;
        unsigned o = 0u;
#pragma unroll
        for (int k = 0; k < 9; ++k) o |= sdh[dr + k][j];
        sdv[dr][j] = o;
    }
    __syncthreads();

    // horizontal erode (pad 1 outside image)
    for (int i = tid; i < 72 * 8; i += 512) {
        int dr = i >> 3, ow = i & 7;
        unsigned curw = sdv[dr][ow + 1];
        unsigned left  = (wbase + ow - 1 >= 0)    ? sdv[dr][ow]     : 0xFFFFFFFFu;
        unsigned right = (wbase + ow + 1 < WORDS) ? sdv[dr][ow + 2] : 0xFFFFFFFFu;
        unsigned long long a = ((unsigned long long)curw << 32) | left;
        unsigned long long b = ((unsigned long long)right << 32) | curw;
        unsigned o = curw;
#pragma unroll
        for (int k = 1; k <= 4; ++k) {
            o &= (unsigned)(a >> (32 - k));
            o &= (unsigned)(b >> k);
        }
        seh[dr][ow] = o;
    }
    __syncthreads();

    // vertical erode (pad 1 outside image): out rows 0..63
    for (int i = tid; i < 64 * 8; i += 512) {
        int orow = i >> 3, ow = i & 7;
        unsigned o = 0xFFFFFFFFu;
#pragma unroll
        for (int k = 0; k < 9; ++k) {
            int gr = r0 + orow - 4 + k;
            unsigned v = (gr >= 0 && gr < W) ? seh[orow + k][ow] : 0xFFFFFFFFu;
            o &= v;
        }
        sfw[orow][ow] = o;
    }
    __syncthreads();

    // expand to f32, float4 stores (64 rows x 64 quads)
    float4* out4 = (float4*)out;
    for (int i = tid; i < 64 * 64; i += 512) {
        int orow = i >> 6;
        int c = (i & 63) << 2;
        unsigned wv = sfw[orow][c >> 5];
        int sh = c & 31;
        float4 o;
        o.x = ((wv >> (sh + 0)) & 1u) ? 1.0f : 0.0f;
        o.y = ((wv >> (sh + 1)) & 1u) ? 1.0f : 0.0f;
        o.z = ((wv >> (sh + 2)) & 1u) ? 1.0f : 0.0f;
        o.w = ((wv >> (sh + 3)) & 1u) ? 1.0f : 0.0f;
        out4[(((r0 + orow) << 11) + (wbase << 5) + c) >> 2] = o;
    }
}

// ---------------------------------------------------------------------------
extern "C" void kernel_launch(void* const* d_in, const int* in_sizes, int n_in,
                              void* d_out, int out_size) {
    const float* x  = (const float*)d_in[0];
    const float* bk = (const float*)d_in[1];
    float* out = (float*)d_out;

    dim3 gblur(W / 64, W / 32);
    k_blur<<<gblur, 256>>>(x, bk);
    k_select<<<NPAT, 1024>>>();
    dim3 gclose(8, W / 64);
    k_close<<<gclose, 512>>>(out);
}